// round 7
// baseline (speedup 1.0000x reference)
#include <cuda_runtime.h>
#include <cuda_bf16.h>

#define NF    50
#define DIM   64
#define ATT   64
#define CARDI 10000
#define NPAIR 1225
#define NTHREADS 256
#define MTILE 128
#define NTILES 10
#define BST   144         // bf16 tile row stride in BYTES
#define FSTB  144         // sF (bf16) row stride in BYTES

// ---- dynamic smem byte offsets ----
#define OFF_A0   0                       // A tile buf0: 128 x 144B
#define OFF_A1   (128 * BST)             // A tile buf1
#define OFF_B    (2 * 128 * BST)         // B = W1^T: 64 x 144B
#define OFF_F    (OFF_B + 64 * BST)      // sF bf16: 50 x 144B
#define OFF_LOG  (OFF_F + NF * FSTB)
#define OFF_SUM  (OFF_LOG + NPAIR * 4)
#define OFF_SI   (OFF_SUM + NPAIR * 4)
#define OFF_SJ   (OFF_SI + 1232)
#define SMEM_DYN (OFF_SJ + 1232)

__device__ __forceinline__ unsigned smem_u32(const void* p) {
    unsigned a;
    asm("{ .reg .u64 t; cvta.to.shared.u64 t, %1; cvt.u32.u64 %0, t; }"
        : "=r"(a) : "l"(p));
    return a;
}
__device__ __forceinline__ unsigned bf2(float lo, float hi) {
    unsigned r;
    asm("cvt.rn.bf16x2.f32 %0, %1, %2;" : "=r"(r) : "f"(hi), "f"(lo));
    return r;
}
__device__ __forceinline__ unsigned hmul2(unsigned a, unsigned b) {
    unsigned r;
    asm("mul.rn.bf16x2 %0, %1, %2;" : "=r"(r) : "r"(a), "r"(b));
    return r;
}
__device__ __forceinline__ void ldsm4(unsigned& r0, unsigned& r1,
                                      unsigned& r2, unsigned& r3, unsigned addr) {
    asm volatile("ldmatrix.sync.aligned.m8n8.x4.shared.b16 {%0,%1,%2,%3}, [%4];"
                 : "=r"(r0), "=r"(r1), "=r"(r2), "=r"(r3) : "r"(addr));
}
__device__ __forceinline__ void mma16816(float4& d,
                                         unsigned a0, unsigned a1, unsigned a2, unsigned a3,
                                         unsigned b0, unsigned b1) {
    asm volatile(
        "mma.sync.aligned.m16n8k16.row.col.f32.bf16.bf16.f32 "
        "{%0,%1,%2,%3}, {%4,%5,%6,%7}, {%8,%9}, {%0,%1,%2,%3};"
        : "+f"(d.x), "+f"(d.y), "+f"(d.z), "+f"(d.w)
        : "r"(a0), "r"(a1), "r"(a2), "r"(a3), "r"(b0), "r"(b1));
}

// build half-row of A tile: thread covers 32 k's (64B) of pair p
__device__ __forceinline__ void build_half(char* sb, int t, int tid) {
    int r = tid >> 1, dh = tid & 1;
    int p = t * MTILE + r;
    char* A = sb + ((t & 1) ? OFF_A1 : OFF_A0) + r * BST + dh * 64;
    const unsigned char* si = (const unsigned char*)(sb + OFF_SI);
    const unsigned char* sj = (const unsigned char*)(sb + OFF_SJ);
    if (p < NPAIR) {
        const uint4* fi = (const uint4*)(sb + OFF_F + si[p] * FSTB + dh * 64);
        const uint4* fj = (const uint4*)(sb + OFF_F + sj[p] * FSTB + dh * 64);
        #pragma unroll
        for (int q = 0; q < 4; q++) {
            uint4 a = fi[q], c = fj[q];
            *(uint4*)(A + q * 16) = make_uint4(hmul2(a.x, c.x), hmul2(a.y, c.y),
                                               hmul2(a.z, c.z), hmul2(a.w, c.w));
        }
    } else {
        #pragma unroll
        for (int q = 0; q < 4; q++)
            *(uint4*)(A + q * 16) = make_uint4(0, 0, 0, 0);
    }
}

__global__ __launch_bounds__(NTHREADS, 2)
void afm_kernel(const int* __restrict__ x32,
                const float* __restrict__ emb,
                const float* __restrict__ W1,
                const float* __restrict__ b1,
                const float* __restrict__ w2,
                const float* __restrict__ b2,
                const float* __restrict__ lin_w,
                const float* __restrict__ lin_b,
                float* __restrict__ out)
{
    extern __shared__ __align__(16) char sb[];
    float* slog  = (float*)(sb + OFF_LOG);
    float* ssum  = (float*)(sb + OFF_SUM);
    unsigned char* si = (unsigned char*)(sb + OFF_SI);
    unsigned char* sj = (unsigned char*)(sb + OFF_SJ);
    const unsigned sbase = smem_u32(sb);

    __shared__ float sb1[ATT], sw2[ATT], sLinA[64], sRed[32], sM;

    const int b = blockIdx.x, tid = threadIdx.x;
    const int wid = tid >> 5, lane = tid & 31;

    // int32 vs int64 index dtype probe (values < 5e5 -> int64 high words zero)
    const bool is64 = (x32[1] == 0) & (x32[3] == 0) & (x32[5] == 0) & (x32[7] == 0);
    const long long* x64 = (const long long*)x32;

    // ---- Phase A: stage embeddings (bf16), B = W1^T bf16, biases, tables ----
    for (int q = tid; q < NF * DIM / 4; q += NTHREADS) {
        int row = q >> 4, c4 = q & 15;
        long long xv = is64 ? x64[(long long)b * NF + row]
                            : (long long)x32[b * NF + row];
        int gidx = (int)xv + row * CARDI;
        float4 v = ((const float4*)(emb + (long long)gidx * DIM))[c4];
        uint2 o = make_uint2(bf2(v.x, v.y), bf2(v.z, v.w));
        *(uint2*)(sb + OFF_F + row * FSTB + c4 * 8) = o;
    }
    {   // B[n][k] = W1[k][n] bf16, row stride 144B
        int n = tid & 63, kg = tid >> 6;
        unsigned u[8];
        #pragma unroll
        for (int e = 0; e < 8; e++) {
            float w0 = W1[(kg * 16 + 2 * e) * ATT + n];
            float w1v = W1[(kg * 16 + 2 * e + 1) * ATT + n];
            u[e] = bf2(w0, w1v);
        }
        char* dst = sb + OFF_B + n * BST + kg * 32;
        *(uint4*)(dst)      = make_uint4(u[0], u[1], u[2], u[3]);
        *(uint4*)(dst + 16) = make_uint4(u[4], u[5], u[6], u[7]);
    }
    if (tid < ATT) { sb1[tid] = b1[tid]; sw2[tid] = w2[tid]; }
    if (tid < 64) sLinA[tid] = 0.0f;
    if (tid < NF) {
        long long xv = is64 ? x64[(long long)b * NF + tid]
                            : (long long)x32[b * NF + tid];
        sLinA[tid] = lin_w[(int)xv + tid * CARDI];
    }
    for (int p = tid; p < NPAIR; p += NTHREADS) {
        int i = (int)((99.0f - sqrtf(9801.0f - 8.0f * (float)p)) * 0.5f);
        i = min(max(i, 0), 48);
        while (i * (99 - i) / 2 > p) --i;
        while ((i + 1) * (98 - i) / 2 <= p) ++i;
        si[p] = (unsigned char)i;
        sj[p] = (unsigned char)(i + 1 + (p - i * (99 - i) / 2));
    }

    const int m0 = wid * 16;
    const int g  = lane >> 2;
    const unsigned aArow0 = sbase + OFF_A0 + (m0 + (lane & 15)) * BST + (lane >> 4) * 16;
    const unsigned aArow1 = aArow0 + (OFF_A1 - OFF_A0);
    const unsigned aBrow  = sbase + OFF_B + ((lane >> 4) * 8 + (lane & 7)) * BST
                                  + ((lane >> 3) & 1) * 16;
    const unsigned onesf = (lane < 4) ? 0x3F803F80u : 0u;   // ones-column B fragment

    __syncthreads();

    // ---- preload all B fragments (invariant across tiles) ----
    unsigned Bf[4][4][4];
    #pragma unroll
    for (int kk = 0; kk < 4; kk++)
        #pragma unroll
        for (int jp = 0; jp < 4; jp++)
            ldsm4(Bf[kk][jp][0], Bf[kk][jp][1], Bf[kk][jp][2], Bf[kk][jp][3],
                  aBrow + (jp * 16) * BST + kk * 32);

    // ---- prologue: build tile 0, load its A fragments ----
    build_half(sb, 0, tid);
    __syncthreads();

    unsigned af[4][4];     // A fragments for current tile [kk][reg]
    #pragma unroll
    for (int kk = 0; kk < 4; kk++)
        ldsm4(af[kk][0], af[kk][1], af[kk][2], af[kk][3], aArow0 + kk * 32);

    // ---- pipelined tiles: build(t+1) | HMMA(t)+epilogue(t) ----
    for (int t = 0; t < NTILES; t++) {
        if (t + 1 < NTILES) build_half(sb, t + 1, tid);   // LSU work, other buffer

        float4 acc[8];
        float4 accS = make_float4(0.f, 0.f, 0.f, 0.f);
        #pragma unroll
        for (int j = 0; j < 8; j++) acc[j] = make_float4(0.f, 0.f, 0.f, 0.f);

        #pragma unroll
        for (int kk = 0; kk < 4; kk++) {
            #pragma unroll
            for (int jp = 0; jp < 4; jp++) {
                mma16816(acc[2 * jp],     af[kk][0], af[kk][1], af[kk][2], af[kk][3],
                         Bf[kk][jp][0], Bf[kk][jp][1]);
                mma16816(acc[2 * jp + 1], af[kk][0], af[kk][1], af[kk][2], af[kk][3],
                         Bf[kk][jp][2], Bf[kk][jp][3]);
            }
            mma16816(accS, af[kk][0], af[kk][1], af[kk][2], af[kk][3], onesf, onesf);
        }

        // epilogue: relu + dot(w2), quad-reduce; logits + inter_sum
        float pl0 = 0.f, pl1 = 0.f;
        #pragma unroll
        for (int j = 0; j < 8; j++) {
            int c0 = j * 8 + (lane & 3) * 2;
            float2 bb = *(const float2*)(sb1 + c0);
            float2 ww = *(const float2*)(sw2 + c0);
            pl0 = fmaf(fmaxf(acc[j].x + bb.x, 0.f), ww.x, pl0);
            pl0 = fmaf(fmaxf(acc[j].y + bb.y, 0.f), ww.y, pl0);
            pl1 = fmaf(fmaxf(acc[j].z + bb.x, 0.f), ww.x, pl1);
            pl1 = fmaf(fmaxf(acc[j].w + bb.y, 0.f), ww.y, pl1);
        }
        #pragma unroll
        for (int o = 1; o <= 2; o <<= 1) {
            pl0 += __shfl_xor_sync(0xffffffffu, pl0, o);
            pl1 += __shfl_xor_sync(0xffffffffu, pl1, o);
        }
        if ((lane & 3) == 0) {
            int p = t * MTILE + m0 + g;
            if (p < NPAIR)     { slog[p]     = pl0; ssum[p]     = accS.x; }
            if (p + 8 < NPAIR) { slog[p + 8] = pl1; ssum[p + 8] = accS.z; }
        }

        __syncthreads();    // build(t+1) complete everywhere

        if (t + 1 < NTILES) {
            const unsigned aA = ((t + 1) & 1) ? aArow1 : aArow0;
            #pragma unroll
            for (int kk = 0; kk < 4; kk++)
                ldsm4(af[kk][0], af[kk][1], af[kk][2], af[kk][3], aA + kk * 32);
        }
    }

    // ---- softmax over pairs + combine ----
    float m = -1e30f;
    for (int p = tid; p < NPAIR; p += NTHREADS) m = fmaxf(m, slog[p]);
    #pragma unroll
    for (int o = 16; o; o >>= 1) m = fmaxf(m, __shfl_xor_sync(0xffffffffu, m, o));
    if (lane == 0) sRed[wid] = m;
    __syncthreads();
    if (tid < 32) {
        float tv = (tid < NTHREADS / 32) ? sRed[tid] : -1e30f;
        #pragma unroll
        for (int o = 4; o; o >>= 1) tv = fmaxf(tv, __shfl_xor_sync(0xffffffffu, tv, o));
        if (tid == 0) sM = tv;
    }
    __syncthreads();
    const float M = sM;

    float es = 0.0f, ws = 0.0f;
    for (int p = tid; p < NPAIR; p += NTHREADS) {
        float e = __expf(slog[p] - M);
        es += e;
        ws = fmaf(e, ssum[p], ws);
    }
    #pragma unroll
    for (int o = 16; o; o >>= 1) {
        es += __shfl_xor_sync(0xffffffffu, es, o);
        ws += __shfl_xor_sync(0xffffffffu, ws, o);
    }
    if (lane == 0) { sRed[wid] = es; sRed[16 + wid] = ws; }
    __syncthreads();
    if (tid == 0) {
        float ES = 0.0f, WS = 0.0f;
        #pragma unroll
        for (int w = 0; w < NTHREADS / 32; w++) { ES += sRed[w]; WS += sRed[16 + w]; }
        float lin = lin_b[0];
        #pragma unroll
        for (int f = 0; f < NF; f++) lin += sLinA[f];
        out[b] = lin + WS / ES;
    }
}

extern "C" void kernel_launch(void* const* d_in, const int* in_sizes, int n_in,
                              void* d_out, int out_size)
{
    const int*   x     = (const int*)d_in[0];
    const float* emb   = (const float*)d_in[1];
    const float* W1    = (const float*)d_in[2];
    const float* b1    = (const float*)d_in[3];
    const float* w2    = (const float*)d_in[4];
    const float* b2    = (const float*)d_in[5];
    const float* lin_w = (const float*)d_in[6];
    const float* lin_b = (const float*)d_in[7];
    float* out = (float*)d_out;

    static int configured = 0;
    if (!configured) {
        cudaFuncSetAttribute(afm_kernel, cudaFuncAttributeMaxDynamicSharedMemorySize,
                             SMEM_DYN);
        configured = 1;
    }
    afm_kernel<<<out_size, NTHREADS, SMEM_DYN>>>(x, emb, W1, b1, w2, b2,
                                                 lin_w, lin_b, out);
}

// round 8
// speedup vs baseline: 1.3192x; 1.3192x over previous
#include <cuda_runtime.h>
#include <cuda_bf16.h>

#define NF    50
#define DIM   64
#define ATT   64
#define CARDI 10000
#define NPAIR 1225
#define NTHREADS 256
#define MTILE 128
#define NTILES 10
#define BST   144         // B staging row stride in BYTES
#define FSTB  144         // sF (bf16, fragment-permuted) row stride in BYTES

// ---- dynamic smem byte offsets ----
#define OFF_B    0                        // B = W1^T: 64 x 144B
#define OFF_F    (64 * BST)               // sF: 50 x 144B (permuted words)
#define OFF_LOG  (OFF_F + NF * FSTB)
#define OFF_SUM  (OFF_LOG + NPAIR * 4)
#define OFF_SIJ  (OFF_SUM + NPAIR * 4)    // ushort sij[1232]
#define SMEM_DYN (OFF_SIJ + 1232 * 2)

__device__ __forceinline__ unsigned smem_u32(const void* p) {
    unsigned a;
    asm("{ .reg .u64 t; cvta.to.shared.u64 t, %1; cvt.u32.u64 %0, t; }"
        : "=r"(a) : "l"(p));
    return a;
}
__device__ __forceinline__ unsigned bf2(float lo, float hi) {
    unsigned r;
    asm("cvt.rn.bf16x2.f32 %0, %1, %2;" : "=r"(r) : "f"(hi), "f"(lo));
    return r;
}
__device__ __forceinline__ unsigned hmul2(unsigned a, unsigned b) {
    unsigned r;
    asm("mul.rn.bf16x2 %0, %1, %2;" : "=r"(r) : "r"(a), "r"(b));
    return r;
}
__device__ __forceinline__ void ldsm4(unsigned& r0, unsigned& r1,
                                      unsigned& r2, unsigned& r3, unsigned addr) {
    asm volatile("ldmatrix.sync.aligned.m8n8.x4.shared.b16 {%0,%1,%2,%3}, [%4];"
                 : "=r"(r0), "=r"(r1), "=r"(r2), "=r"(r3) : "r"(addr));
}
__device__ __forceinline__ void mma16816(float4& d,
                                         unsigned a0, unsigned a1, unsigned a2, unsigned a3,
                                         unsigned b0, unsigned b1) {
    asm volatile(
        "mma.sync.aligned.m16n8k16.row.col.f32.bf16.bf16.f32 "
        "{%0,%1,%2,%3}, {%4,%5,%6,%7}, {%8,%9}, {%0,%1,%2,%3};"
        : "+f"(d.x), "+f"(d.y), "+f"(d.z), "+f"(d.w)
        : "r"(a0), "r"(a1), "r"(a2), "r"(a3), "r"(b0), "r"(b1));
}

__global__ __launch_bounds__(NTHREADS, 2)
void afm_kernel(const int* __restrict__ x32,
                const float* __restrict__ emb,
                const float* __restrict__ W1,
                const float* __restrict__ b1,
                const float* __restrict__ w2,
                const float* __restrict__ b2,
                const float* __restrict__ lin_w,
                const float* __restrict__ lin_b,
                float* __restrict__ out)
{
    extern __shared__ __align__(16) char sb[];
    float* slog = (float*)(sb + OFF_LOG);
    float* ssum = (float*)(sb + OFF_SUM);
    unsigned short* sij = (unsigned short*)(sb + OFF_SIJ);
    const unsigned sbase = smem_u32(sb);

    __shared__ float sb1[ATT], sw2[ATT], sLinA[64], sRed[32], sM;

    const int b = blockIdx.x, tid = threadIdx.x;
    const int wid = tid >> 5, lane = tid & 31;

    // int32 vs int64 index dtype probe (values < 5e5 -> int64 high words zero)
    const bool is64 = (x32[1] == 0) & (x32[3] == 0) & (x32[5] == 0) & (x32[7] == 0);
    const long long* x64 = (const long long*)x32;

    // ---- Phase A: stage embeddings in fragment-permuted bf16 layout ----
    // word w (= k/2, 0..31) encodes (kk=w>>3, h=(w>>2)&1, c=w&3);
    // stored at word offset c*8 + kk*2 + h within the row.
    for (int q = tid; q < NF * DIM / 4; q += NTHREADS) {
        int row = q >> 4, c4 = q & 15;
        long long xv = is64 ? x64[(long long)b * NF + row]
                            : (long long)x32[b * NF + row];
        int gidx = (int)xv + row * CARDI;
        float4 v = ((const float4*)(emb + (long long)gidx * DIM))[c4];
        unsigned w0 = bf2(v.x, v.y), w1 = bf2(v.z, v.w);
        unsigned* dst = (unsigned*)(sb + OFF_F + row * FSTB);
        int wa = 2 * c4, wb = 2 * c4 + 1;
        dst[(wa & 3) * 8 + (wa >> 3) * 2 + ((wa >> 2) & 1)] = w0;
        dst[(wb & 3) * 8 + (wb >> 3) * 2 + ((wb >> 2) & 1)] = w1;
    }
    {   // B[n][k] = W1[k][n] bf16, row stride 144B (for ldsm preload)
        int n = tid & 63, kg = tid >> 6;
        unsigned u[8];
        #pragma unroll
        for (int e = 0; e < 8; e++) {
            float w0 = W1[(kg * 16 + 2 * e) * ATT + n];
            float w1v = W1[(kg * 16 + 2 * e + 1) * ATT + n];
            u[e] = bf2(w0, w1v);
        }
        char* dst = sb + OFF_B + n * BST + kg * 32;
        *(uint4*)(dst)      = make_uint4(u[0], u[1], u[2], u[3]);
        *(uint4*)(dst + 16) = make_uint4(u[4], u[5], u[6], u[7]);
    }
    if (tid < ATT) { sb1[tid] = b1[tid]; sw2[tid] = w2[tid]; }
    if (tid < 64) sLinA[tid] = 0.0f;
    if (tid < NF) {
        long long xv = is64 ? x64[(long long)b * NF + tid]
                            : (long long)x32[b * NF + tid];
        sLinA[tid] = lin_w[(int)xv + tid * CARDI];
    }
    for (int p = tid; p < NPAIR; p += NTHREADS) {
        int i = (int)((99.0f - sqrtf(9801.0f - 8.0f * (float)p)) * 0.5f);
        i = min(max(i, 0), 48);
        while (i * (99 - i) / 2 > p) --i;
        while ((i + 1) * (98 - i) / 2 <= p) ++i;
        int j = i + 1 + (p - i * (99 - i) / 2);
        sij[p] = (unsigned short)(i | (j << 8));
    }

    const int m0 = wid * 16;
    const int g  = lane >> 2;
    const int cx = (lane & 3) * 32;      // byte offset of this lane's word block
    const unsigned aBrow = sbase + OFF_B + ((lane >> 4) * 8 + (lane & 7)) * BST
                                 + ((lane >> 3) & 1) * 16;
    const unsigned onesf = (lane < 4) ? 0x3F803F80u : 0u;   // ones-column B fragment

    __syncthreads();

    // ---- preload all B fragments (invariant across tiles) ----
    unsigned Bf[4][4][4];
    #pragma unroll
    for (int kk = 0; kk < 4; kk++)
        #pragma unroll
        for (int jp = 0; jp < 4; jp++)
            ldsm4(Bf[kk][jp][0], Bf[kk][jp][1], Bf[kk][jp][2], Bf[kk][jp][3],
                  aBrow + (jp * 16) * BST + kk * 32);

    // ---- pair tiles: fully warp-independent, no barriers ----
    const char* fbase = sb + OFF_F;
    #pragma unroll 1
    for (int t = 0; t < NTILES; t++) {
        int pb = t * MTILE + m0 + g;
        int q1 = min(pb, NPAIR - 1), q2 = min(pb + 8, NPAIR - 1);
        unsigned s1 = sij[q1], s2 = sij[q2];

        const uint4* fi1 = (const uint4*)(fbase + (s1 & 255) * FSTB + cx);
        const uint4* fj1 = (const uint4*)(fbase + (s1 >> 8)  * FSTB + cx);
        const uint4* fi2 = (const uint4*)(fbase + (s2 & 255) * FSTB + cx);
        const uint4* fj2 = (const uint4*)(fbase + (s2 >> 8)  * FSTB + cx);
        uint4 i1a = fi1[0], i1b = fi1[1];
        uint4 j1a = fj1[0], j1b = fj1[1];
        uint4 i2a = fi2[0], i2b = fi2[1];
        uint4 j2a = fj2[0], j2b = fj2[1];

        // A fragments per k-step: a0={g,klow} a1={g+8,klow} a2={g,khigh} a3={g+8,khigh}
        unsigned af[4][4];
        af[0][0] = hmul2(i1a.x, j1a.x); af[0][2] = hmul2(i1a.y, j1a.y);
        af[0][1] = hmul2(i2a.x, j2a.x); af[0][3] = hmul2(i2a.y, j2a.y);
        af[1][0] = hmul2(i1a.z, j1a.z); af[1][2] = hmul2(i1a.w, j1a.w);
        af[1][1] = hmul2(i2a.z, j2a.z); af[1][3] = hmul2(i2a.w, j2a.w);
        af[2][0] = hmul2(i1b.x, j1b.x); af[2][2] = hmul2(i1b.y, j1b.y);
        af[2][1] = hmul2(i2b.x, j2b.x); af[2][3] = hmul2(i2b.w == 0 ? j2b.y : j2b.y, 0); // placeholder removed below
        af[2][3] = hmul2(i2b.y, j2b.y);
        af[3][0] = hmul2(i1b.z, j1b.z); af[3][2] = hmul2(i1b.w, j1b.w);
        af[3][1] = hmul2(i2b.z, j2b.z); af[3][3] = hmul2(i2b.w, j2b.w);

        float4 acc[8];
        float4 accS = make_float4(0.f, 0.f, 0.f, 0.f);
        #pragma unroll
        for (int j = 0; j < 8; j++) acc[j] = make_float4(0.f, 0.f, 0.f, 0.f);

        #pragma unroll
        for (int kk = 0; kk < 4; kk++) {
            #pragma unroll
            for (int jp = 0; jp < 4; jp++) {
                mma16816(acc[2 * jp],     af[kk][0], af[kk][1], af[kk][2], af[kk][3],
                         Bf[kk][jp][0], Bf[kk][jp][1]);
                mma16816(acc[2 * jp + 1], af[kk][0], af[kk][1], af[kk][2], af[kk][3],
                         Bf[kk][jp][2], Bf[kk][jp][3]);
            }
            mma16816(accS, af[kk][0], af[kk][1], af[kk][2], af[kk][3], onesf, onesf);
        }

        // epilogue: relu + dot(w2), quad-reduce; logits + inter_sum
        float pl0 = 0.f, pl1 = 0.f;
        #pragma unroll
        for (int j = 0; j < 8; j++) {
            int c0 = j * 8 + (lane & 3) * 2;
            float2 bb = *(const float2*)(sb1 + c0);
            float2 ww = *(const float2*)(sw2 + c0);
            pl0 = fmaf(fmaxf(acc[j].x + bb.x, 0.f), ww.x, pl0);
            pl0 = fmaf(fmaxf(acc[j].y + bb.y, 0.f), ww.y, pl0);
            pl1 = fmaf(fmaxf(acc[j].z + bb.x, 0.f), ww.x, pl1);
            pl1 = fmaf(fmaxf(acc[j].w + bb.y, 0.f), ww.y, pl1);
        }
        #pragma unroll
        for (int o = 1; o <= 2; o <<= 1) {
            pl0 += __shfl_xor_sync(0xffffffffu, pl0, o);
            pl1 += __shfl_xor_sync(0xffffffffu, pl1, o);
        }
        if ((lane & 3) == 0) {
            if (pb < NPAIR)     { slog[pb]     = pl0; ssum[pb]     = accS.x; }
            if (pb + 8 < NPAIR) { slog[pb + 8] = pl1; ssum[pb + 8] = accS.z; }
        }
    }
    __syncthreads();

    // ---- softmax over pairs + combine ----
    float m = -1e30f;
    for (int p = tid; p < NPAIR; p += NTHREADS) m = fmaxf(m, slog[p]);
    #pragma unroll
    for (int o = 16; o; o >>= 1) m = fmaxf(m, __shfl_xor_sync(0xffffffffu, m, o));
    if (lane == 0) sRed[wid] = m;
    __syncthreads();
    if (tid < 32) {
        float tv = (tid < NTHREADS / 32) ? sRed[tid] : -1e30f;
        #pragma unroll
        for (int o = 4; o; o >>= 1) tv = fmaxf(tv, __shfl_xor_sync(0xffffffffu, tv, o));
        if (tid == 0) sM = tv;
    }
    __syncthreads();
    const float M = sM;

    float es = 0.0f, ws = 0.0f;
    for (int p = tid; p < NPAIR; p += NTHREADS) {
        float e = __expf(slog[p] - M);
        es += e;
        ws = fmaf(e, ssum[p], ws);
    }
    #pragma unroll
    for (int o = 16; o; o >>= 1) {
        es += __shfl_xor_sync(0xffffffffu, es, o);
        ws += __shfl_xor_sync(0xffffffffu, ws, o);
    }
    if (lane == 0) { sRed[wid] = es; sRed[16 + wid] = ws; }
    __syncthreads();
    if (tid == 0) {
        float ES = 0.0f, WS = 0.0f;
        #pragma unroll
        for (int w = 0; w < NTHREADS / 32; w++) { ES += sRed[w]; WS += sRed[16 + w]; }
        float lin = lin_b[0];
        #pragma unroll
        for (int f = 0; f < NF; f++) lin += sLinA[f];
        out[b] = lin + WS / ES;
    }
}

extern "C" void kernel_launch(void* const* d_in, const int* in_sizes, int n_in,
                              void* d_out, int out_size)
{
    const int*   x     = (const int*)d_in[0];
    const float* emb   = (const float*)d_in[1];
    const float* W1    = (const float*)d_in[2];
    const float* b1    = (const float*)d_in[3];
    const float* w2    = (const float*)d_in[4];
    const float* b2    = (const float*)d_in[5];
    const float* lin_w = (const float*)d_in[6];
    const float* lin_b = (const float*)d_in[7];
    float* out = (float*)d_out;

    static int configured = 0;
    if (!configured) {
        cudaFuncSetAttribute(afm_kernel, cudaFuncAttributeMaxDynamicSharedMemorySize,
                             SMEM_DYN);
        configured = 1;
    }
    afm_kernel<<<out_size, NTHREADS, SMEM_DYN>>>(x, emb, W1, b1, w2, b2,
                                                 lin_w, lin_b, out);
}

// round 10
// speedup vs baseline: 1.3287x; 1.0073x over previous
#include <cuda_runtime.h>
#include <cuda_bf16.h>

#define NF    50
#define DIM   64
#define ATT   64
#define CARDI 10000
#define NPAIR 1225
#define NTHREADS 256
#define MTILE 128
#define NTILES 10
#define BST   144         // B staging row stride in BYTES
#define FSTB  144         // sF (bf16, fragment-permuted) row stride in BYTES

#define ALIGN16(x) (((x) + 15) & ~15)

// ---- dynamic smem byte offsets (all 16B-aligned) ----
#define OFF_B    0                               // B = W1^T: 64 x 144B
#define OFF_F    (64 * BST)                      // sF: 50 x 144B (permuted words)
#define OFF_LOG  ALIGN16(OFF_F + NF * FSTB)
#define OFF_SUM  ALIGN16(OFF_LOG + NPAIR * 4)
#define OFF_SIJ  ALIGN16(OFF_SUM + NPAIR * 4)    // ushort sij[1232]
#define OFF_W2F  ALIGN16(OFF_SIJ + 1232 * 2)     // w2 B-fragment table [4][8] words
#define OFF_B1F  ALIGN16(OFF_W2F + 128)          // b1 A-bias table [4][8] words
#define SMEM_DYN ALIGN16(OFF_B1F + 128)

__device__ __forceinline__ unsigned smem_u32(const void* p) {
    unsigned a;
    asm("{ .reg .u64 t; cvta.to.shared.u64 t, %1; cvt.u32.u64 %0, t; }"
        : "=r"(a) : "l"(p));
    return a;
}
__device__ __forceinline__ unsigned bf2(float lo, float hi) {
    unsigned r;
    asm("cvt.rn.bf16x2.f32 %0, %1, %2;" : "=r"(r) : "f"(hi), "f"(lo));
    return r;
}
__device__ __forceinline__ unsigned hmul2(unsigned a, unsigned b) {
    unsigned r;
    asm("mul.rn.bf16x2 %0, %1, %2;" : "=r"(r) : "r"(a), "r"(b));
    return r;
}
__device__ __forceinline__ unsigned hadd2(unsigned a, unsigned b) {
    unsigned r;
    asm("add.rn.bf16x2 %0, %1, %2;" : "=r"(r) : "r"(a), "r"(b));
    return r;
}
__device__ __forceinline__ unsigned hmax2(unsigned a, unsigned b) {
    unsigned r;
    asm("max.bf16x2 %0, %1, %2;" : "=r"(r) : "r"(a), "r"(b));
    return r;
}
__device__ __forceinline__ void ldsm4(unsigned& r0, unsigned& r1,
                                      unsigned& r2, unsigned& r3, unsigned addr) {
    asm volatile("ldmatrix.sync.aligned.m8n8.x4.shared.b16 {%0,%1,%2,%3}, [%4];"
                 : "=r"(r0), "=r"(r1), "=r"(r2), "=r"(r3) : "r"(addr));
}
__device__ __forceinline__ void mma16816(float4& d,
                                         unsigned a0, unsigned a1, unsigned a2, unsigned a3,
                                         unsigned b0, unsigned b1) {
    asm volatile(
        "mma.sync.aligned.m16n8k16.row.col.f32.bf16.bf16.f32 "
        "{%0,%1,%2,%3}, {%4,%5,%6,%7}, {%8,%9}, {%0,%1,%2,%3};"
        : "+f"(d.x), "+f"(d.y), "+f"(d.z), "+f"(d.w)
        : "r"(a0), "r"(a1), "r"(a2), "r"(a3), "r"(b0), "r"(b1));
}

__global__ __launch_bounds__(NTHREADS, 2)
void afm_kernel(const int* __restrict__ x32,
                const float* __restrict__ emb,
                const float* __restrict__ W1,
                const float* __restrict__ b1,
                const float* __restrict__ w2,
                const float* __restrict__ b2,
                const float* __restrict__ lin_w,
                const float* __restrict__ lin_b,
                float* __restrict__ out)
{
    extern __shared__ __align__(16) char sb[];
    float* slog = (float*)(sb + OFF_LOG);
    float* ssum = (float*)(sb + OFF_SUM);
    unsigned short* sij = (unsigned short*)(sb + OFF_SIJ);
    const unsigned sbase = smem_u32(sb);

    __shared__ float sLinA[64], sRed[32], sM;

    const int b = blockIdx.x, tid = threadIdx.x;
    const int wid = tid >> 5, lane = tid & 31;

    // int32 vs int64 index dtype probe (values < 5e5 -> int64 high words zero)
    const bool is64 = (x32[1] == 0) & (x32[3] == 0) & (x32[5] == 0) & (x32[7] == 0);
    const long long* x64 = (const long long*)x32;

    // ---- Phase A: stage embeddings in fragment-permuted bf16 layout ----
    // word w (= k/2) at word offset (w&3)*8 + (w>>3)*2 + ((w>>2)&1)
    for (int q = tid; q < NF * DIM / 4; q += NTHREADS) {
        int row = q >> 4, c4 = q & 15;
        long long xv = is64 ? x64[(long long)b * NF + row]
                            : (long long)x32[b * NF + row];
        int gidx = (int)xv + row * CARDI;
        float4 v = ((const float4*)(emb + (long long)gidx * DIM))[c4];
        unsigned w0 = bf2(v.x, v.y), w1 = bf2(v.z, v.w);
        unsigned* dst = (unsigned*)(sb + OFF_F + row * FSTB);
        int wa = 2 * c4, wb = 2 * c4 + 1;
        dst[(wa & 3) * 8 + (wa >> 3) * 2 + ((wa >> 2) & 1)] = w0;
        dst[(wb & 3) * 8 + (wb >> 3) * 2 + ((wb >> 2) & 1)] = w1;
    }
    {   // B[n][k] = W1[k][n] bf16, row stride 144B (for ldsm preload)
        int n = tid & 63, kg = tid >> 6;
        unsigned u[8];
        #pragma unroll
        for (int e = 0; e < 8; e++) {
            float w0 = W1[(kg * 16 + 2 * e) * ATT + n];
            float w1v = W1[(kg * 16 + 2 * e + 1) * ATT + n];
            u[e] = bf2(w0, w1v);
        }
        char* dst = sb + OFF_B + n * BST + kg * 32;
        *(uint4*)(dst)      = make_uint4(u[0], u[1], u[2], u[3]);
        *(uint4*)(dst + 16) = make_uint4(u[4], u[5], u[6], u[7]);
    }
    // per-(lane&3) fragment tables for the logit MMA
    if (tid < 4) {
        int c = tid;
        unsigned* wt = (unsigned*)(sb + OFF_W2F) + c * 8;
        unsigned* bt = (unsigned*)(sb + OFF_B1F) + c * 8;
        #pragma unroll
        for (int kk = 0; kk < 4; kk++) {
            wt[kk * 2]     = bf2(w2[16 * kk + 2 * c],     w2[16 * kk + 2 * c + 1]);
            wt[kk * 2 + 1] = bf2(w2[16 * kk + 8 + 2 * c], w2[16 * kk + 8 + 2 * c + 1]);
        }
        #pragma unroll
        for (int j = 0; j < 8; j++)
            bt[j] = bf2(b1[8 * j + 2 * c], b1[8 * j + 2 * c + 1]);
    }
    if (tid < 64) sLinA[tid] = 0.0f;
    if (tid < NF) {
        long long xv = is64 ? x64[(long long)b * NF + tid]
                            : (long long)x32[b * NF + tid];
        sLinA[tid] = lin_w[(int)xv + tid * CARDI];
    }
    for (int p = tid; p < NPAIR; p += NTHREADS) {
        int i = (int)((99.0f - sqrtf(9801.0f - 8.0f * (float)p)) * 0.5f);
        i = min(max(i, 0), 48);
        while (i * (99 - i) / 2 > p) --i;
        while ((i + 1) * (98 - i) / 2 <= p) ++i;
        int j = i + 1 + (p - i * (99 - i) / 2);
        sij[p] = (unsigned short)(i | (j << 8));
    }

    const int m0 = wid * 16;
    const int g  = lane >> 2;
    const int cx = (lane & 3) * 32;      // byte offset of this lane's word block
    const unsigned aBrow = sbase + OFF_B + ((lane >> 4) * 8 + (lane & 7)) * BST
                                 + ((lane >> 3) & 1) * 16;
    const unsigned onesf = (lane < 4) ? 0x3F803F80u : 0u;   // ones-column B fragment

    __syncthreads();

    // ---- preload all B fragments (invariant across tiles) ----
    unsigned Bf[4][4][4];
    #pragma unroll
    for (int kk = 0; kk < 4; kk++)
        #pragma unroll
        for (int jp = 0; jp < 4; jp++)
            ldsm4(Bf[kk][jp][0], Bf[kk][jp][1], Bf[kk][jp][2], Bf[kk][jp][3],
                  aBrow + (jp * 16) * BST + kk * 32);

    // w2 / b1 fragments (invariant across tiles)
    unsigned w2f[8], b1f[8];
    *(uint4*)&w2f[0] = *(const uint4*)(sb + OFF_W2F + (lane & 3) * 32);
    *(uint4*)&w2f[4] = *(const uint4*)(sb + OFF_W2F + (lane & 3) * 32 + 16);
    *(uint4*)&b1f[0] = *(const uint4*)(sb + OFF_B1F + (lane & 3) * 32);
    *(uint4*)&b1f[4] = *(const uint4*)(sb + OFF_B1F + (lane & 3) * 32 + 16);

    // ---- pair tiles: warp-independent, no barriers ----
    const char* fbase = sb + OFF_F;
    #pragma unroll 1
    for (int t = 0; t < NTILES; t++) {
        int pb = t * MTILE + m0 + g;
        int q1 = min(pb, NPAIR - 1), q2 = min(pb + 8, NPAIR - 1);
        unsigned s1 = sij[q1], s2 = sij[q2];

        const uint4* fi1 = (const uint4*)(fbase + (s1 & 255) * FSTB + cx);
        const uint4* fj1 = (const uint4*)(fbase + (s1 >> 8)  * FSTB + cx);
        const uint4* fi2 = (const uint4*)(fbase + (s2 & 255) * FSTB + cx);
        const uint4* fj2 = (const uint4*)(fbase + (s2 >> 8)  * FSTB + cx);
        uint4 i1a = fi1[0], i1b = fi1[1];
        uint4 j1a = fj1[0], j1b = fj1[1];
        uint4 i2a = fi2[0], i2b = fi2[1];
        uint4 j2a = fj2[0], j2b = fj2[1];

        // A fragments per k-step: a0={g,klow} a1={g+8,klow} a2={g,khigh} a3={g+8,khigh}
        unsigned af[4][4];
        af[0][0] = hmul2(i1a.x, j1a.x); af[0][2] = hmul2(i1a.y, j1a.y);
        af[0][1] = hmul2(i2a.x, j2a.x); af[0][3] = hmul2(i2a.y, j2a.y);
        af[1][0] = hmul2(i1a.z, j1a.z); af[1][2] = hmul2(i1a.w, j1a.w);
        af[1][1] = hmul2(i2a.z, j2a.z); af[1][3] = hmul2(i2a.w, j2a.w);
        af[2][0] = hmul2(i1b.x, j1b.x); af[2][2] = hmul2(i1b.y, j1b.y);
        af[2][1] = hmul2(i2b.x, j2b.x); af[2][3] = hmul2(i2b.y, j2b.y);
        af[3][0] = hmul2(i1b.z, j1b.z); af[3][2] = hmul2(i1b.w, j1b.w);
        af[3][1] = hmul2(i2b.z, j2b.z); af[3][3] = hmul2(i2b.w, j2b.w);

        float4 acc[8];
        float4 accS = make_float4(0.f, 0.f, 0.f, 0.f);
        #pragma unroll
        for (int j = 0; j < 8; j++) acc[j] = make_float4(0.f, 0.f, 0.f, 0.f);

        #pragma unroll
        for (int kk = 0; kk < 4; kk++) {
            #pragma unroll
            for (int jp = 0; jp < 4; jp++) {
                mma16816(acc[2 * jp],     af[kk][0], af[kk][1], af[kk][2], af[kk][3],
                         Bf[kk][jp][0], Bf[kk][jp][1]);
                mma16816(acc[2 * jp + 1], af[kk][0], af[kk][1], af[kk][2], af[kk][3],
                         Bf[kk][jp][2], Bf[kk][jp][3]);
            }
            mma16816(accS, af[kk][0], af[kk][1], af[kk][2], af[kk][3], onesf, onesf);
        }

        // -- epilogue on tensor pipe: bias+relu in bf16x2, then logit MMA --
        unsigned hx[8], hz[8];
        #pragma unroll
        for (int j = 0; j < 8; j++) {
            hx[j] = hmax2(hadd2(bf2(acc[j].x, acc[j].y), b1f[j]), 0u);
            hz[j] = hmax2(hadd2(bf2(acc[j].z, acc[j].w), b1f[j]), 0u);
        }
        float4 dlog = make_float4(0.f, 0.f, 0.f, 0.f);
        #pragma unroll
        for (int kk = 0; kk < 4; kk++)
            mma16816(dlog, hx[2 * kk], hz[2 * kk], hx[2 * kk + 1], hz[2 * kk + 1],
                     w2f[2 * kk], w2f[2 * kk + 1]);

        if ((lane & 3) == 0) {
            if (pb < NPAIR)     { slog[pb]     = dlog.x; ssum[pb]     = accS.x; }
            if (pb + 8 < NPAIR) { slog[pb + 8] = dlog.z; ssum[pb + 8] = accS.z; }
        }
    }
    __syncthreads();

    // ---- softmax over pairs + combine ----
    float m = -1e30f;
    for (int p = tid; p < NPAIR; p += NTHREADS) m = fmaxf(m, slog[p]);
    #pragma unroll
    for (int o = 16; o; o >>= 1) m = fmaxf(m, __shfl_xor_sync(0xffffffffu, m, o));
    if (lane == 0) sRed[wid] = m;
    __syncthreads();
    if (tid < 32) {
        float tv = (tid < NTHREADS / 32) ? sRed[tid] : -1e30f;
        #pragma unroll
        for (int o = 4; o; o >>= 1) tv = fmaxf(tv, __shfl_xor_sync(0xffffffffu, tv, o));
        if (tid == 0) sM = tv;
    }
    __syncthreads();
    const float M = sM;

    float es = 0.0f, ws = 0.0f;
    for (int p = tid; p < NPAIR; p += NTHREADS) {
        float e = __expf(slog[p] - M);
        es += e;
        ws = fmaf(e, ssum[p], ws);
    }
    #pragma unroll
    for (int o = 16; o; o >>= 1) {
        es += __shfl_xor_sync(0xffffffffu, es, o);
        ws += __shfl_xor_sync(0xffffffffu, ws, o);
    }
    if (lane == 0) { sRed[wid] = es; sRed[16 + wid] = ws; }
    __syncthreads();
    if (tid == 0) {
        float ES = 0.0f, WS = 0.0f;
        #pragma unroll
        for (int w = 0; w < NTHREADS / 32; w++) { ES += sRed[w]; WS += sRed[16 + w]; }
        float lin = lin_b[0];
        #pragma unroll
        for (int f = 0; f < NF; f++) lin += sLinA[f];
        out[b] = lin + WS / ES;
    }
}

extern "C" void kernel_launch(void* const* d_in, const int* in_sizes, int n_in,
                              void* d_out, int out_size)
{
    const int*   x     = (const int*)d_in[0];
    const float* emb   = (const float*)d_in[1];
    const float* W1    = (const float*)d_in[2];
    const float* b1    = (const float*)d_in[3];
    const float* w2    = (const float*)d_in[4];
    const float* b2    = (const float*)d_in[5];
    const float* lin_w = (const float*)d_in[6];
    const float* lin_b = (const float*)d_in[7];
    float* out = (float*)d_out;

    static int configured = 0;
    if (!configured) {
        cudaFuncSetAttribute(afm_kernel, cudaFuncAttributeMaxDynamicSharedMemorySize,
                             SMEM_DYN);
        configured = 1;
    }
    afm_kernel<<<out_size, NTHREADS, SMEM_DYN>>>(x, emb, W1, b1, w2, b2,
                                                 lin_w, lin_b, out);
}

// round 11
// speedup vs baseline: 1.4166x; 1.0662x over previous
#include <cuda_runtime.h>
#include <cuda_fp16.h>

#define NF    50
#define DIM   64
#define ATT   64
#define CARDI 10000
#define NPAIR 1225
#define NTHREADS 256
#define MTILE 128
#define NTILES 10
#define BST   144         // B staging row stride in BYTES
#define FSTB  144         // sF (f16, fragment-permuted) row stride in BYTES

#define ALIGN16(x) (((x) + 15) & ~15)

// ---- dynamic smem byte offsets (all 16B-aligned) ----
#define OFF_B    0                               // B = W1^T: 64 x 144B
#define OFF_F    (64 * BST)                      // sF: 50 x 144B (permuted words)
#define OFF_LS   ALIGN16(OFF_F + NF * FSTB)      // float2 {logit, sum}[NPAIR]
#define OFF_SIJ  ALIGN16(OFF_LS + NPAIR * 8)     // ushort sij[1232]
#define OFF_W2F  ALIGN16(OFF_SIJ + 1232 * 2)     // w2 B-fragment table [4][8] words
#define OFF_B1F  ALIGN16(OFF_W2F + 128)          // b1 bias table [4][8] words
#define SMEM_DYN ALIGN16(OFF_B1F + 128)

__device__ __forceinline__ unsigned smem_u32(const void* p) {
    unsigned a;
    asm("{ .reg .u64 t; cvta.to.shared.u64 t, %1; cvt.u32.u64 %0, t; }"
        : "=r"(a) : "l"(p));
    return a;
}
__device__ __forceinline__ unsigned h2pack(float lo, float hi) {
    unsigned r;
    asm("cvt.rn.f16x2.f32 %0, %1, %2;" : "=r"(r) : "f"(hi), "f"(lo));
    return r;
}
__device__ __forceinline__ unsigned hmul2(unsigned a, unsigned b) {
    unsigned r;
    asm("mul.rn.f16x2 %0, %1, %2;" : "=r"(r) : "r"(a), "r"(b));
    return r;
}
__device__ __forceinline__ unsigned hadd2(unsigned a, unsigned b) {
    unsigned r;
    asm("add.rn.f16x2 %0, %1, %2;" : "=r"(r) : "r"(a), "r"(b));
    return r;
}
__device__ __forceinline__ unsigned hmax2(unsigned a, unsigned b) {
    unsigned r;
    asm("max.f16x2 %0, %1, %2;" : "=r"(r) : "r"(a), "r"(b));
    return r;
}
__device__ __forceinline__ void ldsm4(unsigned& r0, unsigned& r1,
                                      unsigned& r2, unsigned& r3, unsigned addr) {
    asm volatile("ldmatrix.sync.aligned.m8n8.x4.shared.b16 {%0,%1,%2,%3}, [%4];"
                 : "=r"(r0), "=r"(r1), "=r"(r2), "=r"(r3) : "r"(addr));
}
// f16 inputs, f16 accumulators (packed)
__device__ __forceinline__ void mma_h(unsigned& d0, unsigned& d1,
                                      unsigned a0, unsigned a1, unsigned a2, unsigned a3,
                                      unsigned b0, unsigned b1) {
    asm volatile(
        "mma.sync.aligned.m16n8k16.row.col.f16.f16.f16.f16 "
        "{%0,%1}, {%2,%3,%4,%5}, {%6,%7}, {%0,%1};"
        : "+r"(d0), "+r"(d1)
        : "r"(a0), "r"(a1), "r"(a2), "r"(a3), "r"(b0), "r"(b1));
}
// f16 inputs, f32 accumulators
__device__ __forceinline__ void mma_hf(float4& d,
                                       unsigned a0, unsigned a1, unsigned a2, unsigned a3,
                                       unsigned b0, unsigned b1) {
    asm volatile(
        "mma.sync.aligned.m16n8k16.row.col.f32.f16.f16.f32 "
        "{%0,%1,%2,%3}, {%4,%5,%6,%7}, {%8,%9}, {%0,%1,%2,%3};"
        : "+f"(d.x), "+f"(d.y), "+f"(d.z), "+f"(d.w)
        : "r"(a0), "r"(a1), "r"(a2), "r"(a3), "r"(b0), "r"(b1));
}

__global__ __launch_bounds__(NTHREADS, 2)
void afm_kernel(const int* __restrict__ x32,
                const float* __restrict__ emb,
                const float* __restrict__ W1,
                const float* __restrict__ b1,
                const float* __restrict__ w2,
                const float* __restrict__ b2,
                const float* __restrict__ lin_w,
                const float* __restrict__ lin_b,
                float* __restrict__ out)
{
    extern __shared__ __align__(16) char sb[];
    float2* sLS = (float2*)(sb + OFF_LS);
    unsigned short* sij = (unsigned short*)(sb + OFF_SIJ);
    const unsigned sbase = smem_u32(sb);

    __shared__ float sLinA[64], sRed[32], sM;

    const int b = blockIdx.x, tid = threadIdx.x;
    const int wid = tid >> 5, lane = tid & 31;

    // int32 vs int64 index dtype probe (values < 5e5 -> int64 high words zero)
    const bool is64 = (x32[1] == 0) & (x32[3] == 0) & (x32[5] == 0) & (x32[7] == 0);
    const long long* x64 = (const long long*)x32;

    // ---- Phase A: stage embeddings in fragment-permuted f16 layout ----
    // word w (= k/2) at word offset (w&3)*8 + (w>>3)*2 + ((w>>2)&1)
    for (int q = tid; q < NF * DIM / 4; q += NTHREADS) {
        int row = q >> 4, c4 = q & 15;
        long long xv = is64 ? x64[(long long)b * NF + row]
                            : (long long)x32[b * NF + row];
        int gidx = (int)xv + row * CARDI;
        float4 v = ((const float4*)(emb + (long long)gidx * DIM))[c4];
        unsigned w0 = h2pack(v.x, v.y), w1 = h2pack(v.z, v.w);
        unsigned* dst = (unsigned*)(sb + OFF_F + row * FSTB);
        int wa = 2 * c4, wb = 2 * c4 + 1;
        dst[(wa & 3) * 8 + (wa >> 3) * 2 + ((wa >> 2) & 1)] = w0;
        dst[(wb & 3) * 8 + (wb >> 3) * 2 + ((wb >> 2) & 1)] = w1;
    }
    {   // B[n][k] = W1[k][n] f16, row stride 144B (for ldsm preload)
        int n = tid & 63, kg = tid >> 6;
        unsigned u[8];
        #pragma unroll
        for (int e = 0; e < 8; e++) {
            float w0 = W1[(kg * 16 + 2 * e) * ATT + n];
            float w1v = W1[(kg * 16 + 2 * e + 1) * ATT + n];
            u[e] = h2pack(w0, w1v);
        }
        char* dst = sb + OFF_B + n * BST + kg * 32;
        *(uint4*)(dst)      = make_uint4(u[0], u[1], u[2], u[3]);
        *(uint4*)(dst + 16) = make_uint4(u[4], u[5], u[6], u[7]);
    }
    // per-(lane&3) fragment tables for the logit MMA (f16x2)
    if (tid < 4) {
        int c = tid;
        unsigned* wt = (unsigned*)(sb + OFF_W2F) + c * 8;
        unsigned* bt = (unsigned*)(sb + OFF_B1F) + c * 8;
        #pragma unroll
        for (int kk = 0; kk < 4; kk++) {
            wt[kk * 2]     = h2pack(w2[16 * kk + 2 * c],     w2[16 * kk + 2 * c + 1]);
            wt[kk * 2 + 1] = h2pack(w2[16 * kk + 8 + 2 * c], w2[16 * kk + 8 + 2 * c + 1]);
        }
        #pragma unroll
        for (int j = 0; j < 8; j++)
            bt[j] = h2pack(b1[8 * j + 2 * c], b1[8 * j + 2 * c + 1]);
    }
    if (tid < 64) sLinA[tid] = 0.0f;
    if (tid < NF) {
        long long xv = is64 ? x64[(long long)b * NF + tid]
                            : (long long)x32[b * NF + tid];
        sLinA[tid] = lin_w[(int)xv + tid * CARDI];
    }
    for (int p = tid; p < NPAIR; p += NTHREADS) {
        int i = (int)((99.0f - sqrtf(9801.0f - 8.0f * (float)p)) * 0.5f);
        i = min(max(i, 0), 48);
        while (i * (99 - i) / 2 > p) --i;
        while ((i + 1) * (98 - i) / 2 <= p) ++i;
        int j = i + 1 + (p - i * (99 - i) / 2);
        sij[p] = (unsigned short)(i | (j << 8));
    }

    const int m0 = wid * 16;
    const int g  = lane >> 2;
    const int cx = (lane & 3) * 32;      // byte offset of this lane's word block
    const unsigned aBrow = sbase + OFF_B + ((lane >> 4) * 8 + (lane & 7)) * BST
                                 + ((lane >> 3) & 1) * 16;
    const unsigned onesf = (lane < 4) ? 0x3C003C00u : 0u;   // f16 ones-column fragment

    __syncthreads();

    // ---- preload all B fragments (invariant across tiles) ----
    unsigned Bf[4][4][4];
    #pragma unroll
    for (int kk = 0; kk < 4; kk++)
        #pragma unroll
        for (int jp = 0; jp < 4; jp++)
            ldsm4(Bf[kk][jp][0], Bf[kk][jp][1], Bf[kk][jp][2], Bf[kk][jp][3],
                  aBrow + (jp * 16) * BST + kk * 32);

    // w2 / b1 fragments (invariant across tiles)
    unsigned w2f[8], b1f[8];
    *(uint4*)&w2f[0] = *(const uint4*)(sb + OFF_W2F + (lane & 3) * 32);
    *(uint4*)&w2f[4] = *(const uint4*)(sb + OFF_W2F + (lane & 3) * 32 + 16);
    *(uint4*)&b1f[0] = *(const uint4*)(sb + OFF_B1F + (lane & 3) * 32);
    *(uint4*)&b1f[4] = *(const uint4*)(sb + OFF_B1F + (lane & 3) * 32 + 16);

    // ---- pair tiles: warp-independent, no barriers ----
    const char* fbase = sb + OFF_F;
    #pragma unroll 1
    for (int t = 0; t < NTILES; t++) {
        int pb = t * MTILE + m0 + g;
        int q1 = min(pb, NPAIR - 1), q2 = min(pb + 8, NPAIR - 1);
        unsigned s1 = sij[q1], s2 = sij[q2];

        const uint4* fi1 = (const uint4*)(fbase + (s1 & 255) * FSTB + cx);
        const uint4* fj1 = (const uint4*)(fbase + (s1 >> 8)  * FSTB + cx);
        const uint4* fi2 = (const uint4*)(fbase + (s2 & 255) * FSTB + cx);
        const uint4* fj2 = (const uint4*)(fbase + (s2 >> 8)  * FSTB + cx);
        uint4 i1a = fi1[0], i1b = fi1[1];
        uint4 j1a = fj1[0], j1b = fj1[1];
        uint4 i2a = fi2[0], i2b = fi2[1];
        uint4 j2a = fj2[0], j2b = fj2[1];

        // A fragments per k-step: a0={g,klow} a1={g+8,klow} a2={g,khigh} a3={g+8,khigh}
        unsigned af[4][4];
        af[0][0] = hmul2(i1a.x, j1a.x); af[0][2] = hmul2(i1a.y, j1a.y);
        af[0][1] = hmul2(i2a.x, j2a.x); af[0][3] = hmul2(i2a.y, j2a.y);
        af[1][0] = hmul2(i1a.z, j1a.z); af[1][2] = hmul2(i1a.w, j1a.w);
        af[1][1] = hmul2(i2a.z, j2a.z); af[1][3] = hmul2(i2a.w, j2a.w);
        af[2][0] = hmul2(i1b.x, j1b.x); af[2][2] = hmul2(i1b.y, j1b.y);
        af[2][1] = hmul2(i2b.x, j2b.x); af[2][3] = hmul2(i2b.y, j2b.y);
        af[3][0] = hmul2(i1b.z, j1b.z); af[3][2] = hmul2(i1b.w, j1b.w);
        af[3][1] = hmul2(i2b.z, j2b.z); af[3][3] = hmul2(i2b.w, j2b.w);

        // main MMA: f16 accumulators, 8 n-tiles
        uint2 acc[8];
        #pragma unroll
        for (int j = 0; j < 8; j++) acc[j] = make_uint2(0u, 0u);
        float4 accS0 = make_float4(0.f, 0.f, 0.f, 0.f);
        float4 accS1 = make_float4(0.f, 0.f, 0.f, 0.f);

        #pragma unroll
        for (int kk = 0; kk < 4; kk++) {
            #pragma unroll
            for (int jp = 0; jp < 4; jp++) {
                mma_h(acc[2 * jp].x,     acc[2 * jp].y,
                      af[kk][0], af[kk][1], af[kk][2], af[kk][3],
                      Bf[kk][jp][0], Bf[kk][jp][1]);
                mma_h(acc[2 * jp + 1].x, acc[2 * jp + 1].y,
                      af[kk][0], af[kk][1], af[kk][2], af[kk][3],
                      Bf[kk][jp][2], Bf[kk][jp][3]);
            }
            if (kk < 2) mma_hf(accS0, af[kk][0], af[kk][1], af[kk][2], af[kk][3], onesf, onesf);
            else        mma_hf(accS1, af[kk][0], af[kk][1], af[kk][2], af[kk][3], onesf, onesf);
        }

        // epilogue: bias+relu in-place (f16x2), then split logit MMA
        unsigned hx[8], hz[8];
        #pragma unroll
        for (int j = 0; j < 8; j++) {
            hx[j] = hmax2(hadd2(acc[j].x, b1f[j]), 0u);
            hz[j] = hmax2(hadd2(acc[j].y, b1f[j]), 0u);
        }
        float4 dl0 = make_float4(0.f, 0.f, 0.f, 0.f);
        float4 dl1 = make_float4(0.f, 0.f, 0.f, 0.f);
        #pragma unroll
        for (int kk = 0; kk < 4; kk++) {
            float4& d = (kk < 2) ? dl0 : dl1;
            mma_hf(d, hx[2 * kk], hz[2 * kk], hx[2 * kk + 1], hz[2 * kk + 1],
                   w2f[2 * kk], w2f[2 * kk + 1]);
        }

        if ((lane & 3) == 0) {
            if (pb < NPAIR)
                sLS[pb]     = make_float2(dl0.x + dl1.x, accS0.x + accS1.x);
            if (pb + 8 < NPAIR)
                sLS[pb + 8] = make_float2(dl0.z + dl1.z, accS0.z + accS1.z);
        }
    }
    __syncthreads();

    // ---- softmax over pairs + combine ----
    float m = -1e30f;
    for (int p = tid; p < NPAIR; p += NTHREADS) m = fmaxf(m, sLS[p].x);
    #pragma unroll
    for (int o = 16; o; o >>= 1) m = fmaxf(m, __shfl_xor_sync(0xffffffffu, m, o));
    if (lane == 0) sRed[wid] = m;
    __syncthreads();
    if (tid < 32) {
        float tv = (tid < NTHREADS / 32) ? sRed[tid] : -1e30f;
        #pragma unroll
        for (int o = 4; o; o >>= 1) tv = fmaxf(tv, __shfl_xor_sync(0xffffffffu, tv, o));
        if (tid == 0) sM = tv;
    }
    __syncthreads();
    const float M = sM;

    float es = 0.0f, ws = 0.0f;
    for (int p = tid; p < NPAIR; p += NTHREADS) {
        float2 ls = sLS[p];
        float e = __expf(ls.x - M);
        es += e;
        ws = fmaf(e, ls.y, ws);
    }
    #pragma unroll
    for (int o = 16; o; o >>= 1) {
        es += __shfl_xor_sync(0xffffffffu, es, o);
        ws += __shfl_xor_sync(0xffffffffu, ws, o);
    }
    if (lane == 0) { sRed[wid] = es; sRed[16 + wid] = ws; }
    __syncthreads();
    if (tid == 0) {
        float ES = 0.0f, WS = 0.0f;
        #pragma unroll
        for (int w = 0; w < NTHREADS / 32; w++) { ES += sRed[w]; WS += sRed[16 + w]; }
        float lin = lin_b[0];
        #pragma unroll
        for (int f = 0; f < NF; f++) lin += sLinA[f];
        out[b] = lin + WS / ES;
    }
}

extern "C" void kernel_launch(void* const* d_in, const int* in_sizes, int n_in,
                              void* d_out, int out_size)
{
    const int*   x     = (const int*)d_in[0];
    const float* emb   = (const float*)d_in[1];
    const float* W1    = (const float*)d_in[2];
    const float* b1    = (const float*)d_in[3];
    const float* w2    = (const float*)d_in[4];
    const float* b2    = (const float*)d_in[5];
    const float* lin_w = (const float*)d_in[6];
    const float* lin_b = (const float*)d_in[7];
    float* out = (float*)d_out;

    static int configured = 0;
    if (!configured) {
        cudaFuncSetAttribute(afm_kernel, cudaFuncAttributeMaxDynamicSharedMemorySize,
                             SMEM_DYN);
        configured = 1;
    }
    afm_kernel<<<out_size, NTHREADS, SMEM_DYN>>>(x, emb, W1, b1, w2, b2,
                                                 lin_w, lin_b, out);
}

// round 12
// speedup vs baseline: 1.4543x; 1.0266x over previous
#include <cuda_runtime.h>
#include <cuda_fp16.h>

#define NF    50
#define DIM   64
#define ATT   64
#define CARDI 10000
#define NPAIR 1225
#define NPAIRP 1232
#define NTHREADS 256
#define MTILE 128
#define NTILES 10
#define BST   144
#define FSTB  144

#define ALIGN16(x) (((x) + 15) & ~15)

// ---- dynamic smem byte offsets (all 16B-aligned) ----
#define OFF_B    0                               // B = W1^T: 64 x 144B
#define OFF_F    (64 * BST)                      // sF: 100 x 144B (2 rows of 50)
#define OFF_LS   ALIGN16(OFF_F + 2 * NF * FSTB)  // float2 {logit,sum}[2*NPAIRP]
#define OFF_SIJ  ALIGN16(OFF_LS + 2 * NPAIRP * 8)
#define OFF_W2F  ALIGN16(OFF_SIJ + NPAIRP * 2)
#define OFF_B1F  ALIGN16(OFF_W2F + 128)
#define SMEM_DYN ALIGN16(OFF_B1F + 128)

__device__ __forceinline__ unsigned smem_u32(const void* p) {
    unsigned a;
    asm("{ .reg .u64 t; cvta.to.shared.u64 t, %1; cvt.u32.u64 %0, t; }"
        : "=r"(a) : "l"(p));
    return a;
}
__device__ __forceinline__ unsigned h2pack(float lo, float hi) {
    unsigned r;
    asm("cvt.rn.f16x2.f32 %0, %1, %2;" : "=r"(r) : "f"(hi), "f"(lo));
    return r;
}
__device__ __forceinline__ unsigned hmul2(unsigned a, unsigned b) {
    unsigned r;
    asm("mul.rn.f16x2 %0, %1, %2;" : "=r"(r) : "r"(a), "r"(b));
    return r;
}
__device__ __forceinline__ unsigned hadd2(unsigned a, unsigned b) {
    unsigned r;
    asm("add.rn.f16x2 %0, %1, %2;" : "=r"(r) : "r"(a), "r"(b));
    return r;
}
__device__ __forceinline__ unsigned hmax2(unsigned a, unsigned b) {
    unsigned r;
    asm("max.f16x2 %0, %1, %2;" : "=r"(r) : "r"(a), "r"(b));
    return r;
}
__device__ __forceinline__ unsigned hfma2(unsigned a, unsigned b, unsigned c) {
    unsigned r;
    asm("fma.rn.f16x2 %0, %1, %2, %3;" : "=r"(r) : "r"(a), "r"(b), "r"(c));
    return r;
}
__device__ __forceinline__ float2 h2f2(unsigned h) {
    float2 f;
    asm("{ .reg .f16 lo, hi; mov.b32 {lo, hi}, %2;\n\t"
        "cvt.f32.f16 %0, lo; cvt.f32.f16 %1, hi; }"
        : "=f"(f.x), "=f"(f.y) : "r"(h));
    return f;
}
__device__ __forceinline__ void ldsm4(unsigned& r0, unsigned& r1,
                                      unsigned& r2, unsigned& r3, unsigned addr) {
    asm volatile("ldmatrix.sync.aligned.m8n8.x4.shared.b16 {%0,%1,%2,%3}, [%4];"
                 : "=r"(r0), "=r"(r1), "=r"(r2), "=r"(r3) : "r"(addr));
}
__device__ __forceinline__ void mma_h(unsigned& d0, unsigned& d1,
                                      unsigned a0, unsigned a1, unsigned a2, unsigned a3,
                                      unsigned b0, unsigned b1) {
    asm volatile(
        "mma.sync.aligned.m16n8k16.row.col.f16.f16.f16.f16 "
        "{%0,%1}, {%2,%3,%4,%5}, {%6,%7}, {%0,%1};"
        : "+r"(d0), "+r"(d1)
        : "r"(a0), "r"(a1), "r"(a2), "r"(a3), "r"(b0), "r"(b1));
}
__device__ __forceinline__ void mma_hf(float4& d,
                                       unsigned a0, unsigned a1, unsigned a2, unsigned a3,
                                       unsigned b0, unsigned b1) {
    asm volatile(
        "mma.sync.aligned.m16n8k16.row.col.f32.f16.f16.f32 "
        "{%0,%1,%2,%3}, {%4,%5,%6,%7}, {%8,%9}, {%0,%1,%2,%3};"
        : "+f"(d.x), "+f"(d.y), "+f"(d.z), "+f"(d.w)
        : "r"(a0), "r"(a1), "r"(a2), "r"(a3), "r"(b0), "r"(b1));
}

__global__ __launch_bounds__(NTHREADS, 2)
void afm_kernel(const int* __restrict__ x32,
                const float* __restrict__ emb,
                const float* __restrict__ W1,
                const float* __restrict__ b1,
                const float* __restrict__ w2,
                const float* __restrict__ b2,
                const float* __restrict__ lin_w,
                const float* __restrict__ lin_b,
                float* __restrict__ out)
{
    extern __shared__ __align__(16) char sb[];
    float2* sLS = (float2*)(sb + OFF_LS);
    unsigned short* sij = (unsigned short*)(sb + OFF_SIJ);
    const unsigned sbase = smem_u32(sb);

    __shared__ float sLinA[128], sRed[32], sM[2];

    const int b0 = blockIdx.x * 2, tid = threadIdx.x;
    const int wid = tid >> 5, lane = tid & 31;

    // int32 vs int64 index dtype probe (values < 5e5 -> int64 high words zero)
    const bool is64 = (x32[1] == 0) & (x32[3] == 0) & (x32[5] == 0) & (x32[7] == 0);
    const long long* x64 = (const long long*)x32;

    // ---- Phase A: stage embeddings for BOTH rows, fragment-permuted f16 ----
    // word w (= k/2) at word offset (w&3)*8 + (w>>3)*2 + ((w>>2)&1)
    for (int q = tid; q < 2 * NF * DIM / 4; q += NTHREADS) {
        int row = q >> 4, c4 = q & 15;              // row 0..99
        int br = b0 + (row >= NF);
        int fld = (row >= NF) ? row - NF : row;
        long long xv = is64 ? x64[(long long)br * NF + fld]
                            : (long long)x32[br * NF + fld];
        int gidx = (int)xv + fld * CARDI;
        float4 v = ((const float4*)(emb + (long long)gidx * DIM))[c4];
        unsigned w0 = h2pack(v.x, v.y), w1 = h2pack(v.z, v.w);
        unsigned* dst = (unsigned*)(sb + OFF_F + row * FSTB);
        int wa = 2 * c4, wb = 2 * c4 + 1;
        dst[(wa & 3) * 8 + (wa >> 3) * 2 + ((wa >> 2) & 1)] = w0;
        dst[(wb & 3) * 8 + (wb >> 3) * 2 + ((wb >> 2) & 1)] = w1;
    }
    {   // B[n][k] = W1[k][n] f16, row stride 144B
        int n = tid & 63, kg = tid >> 6;
        unsigned u[8];
        #pragma unroll
        for (int e = 0; e < 8; e++) {
            float w0 = W1[(kg * 16 + 2 * e) * ATT + n];
            float w1v = W1[(kg * 16 + 2 * e + 1) * ATT + n];
            u[e] = h2pack(w0, w1v);
        }
        char* dst = sb + OFF_B + n * BST + kg * 32;
        *(uint4*)(dst)      = make_uint4(u[0], u[1], u[2], u[3]);
        *(uint4*)(dst + 16) = make_uint4(u[4], u[5], u[6], u[7]);
    }
    // per-(lane&3) tables: w2 pairs matching acc[j] col packing; b1 likewise
    if (tid < 4) {
        int c = tid;
        unsigned* wt = (unsigned*)(sb + OFF_W2F) + c * 8;
        unsigned* bt = (unsigned*)(sb + OFF_B1F) + c * 8;
        #pragma unroll
        for (int j = 0; j < 8; j++) {
            wt[j] = h2pack(w2[8 * j + 2 * c], w2[8 * j + 2 * c + 1]);
            bt[j] = h2pack(b1[8 * j + 2 * c], b1[8 * j + 2 * c + 1]);
        }
    }
    if (tid < 128) sLinA[tid] = 0.0f;
    if (tid < NF) {
        long long xv = is64 ? x64[(long long)b0 * NF + tid]
                            : (long long)x32[b0 * NF + tid];
        sLinA[tid] = lin_w[(int)xv + tid * CARDI];
    } else if (tid >= 64 && tid < 64 + NF) {
        int fld = tid - 64;
        long long xv = is64 ? x64[(long long)(b0 + 1) * NF + fld]
                            : (long long)x32[(b0 + 1) * NF + fld];
        sLinA[tid] = lin_w[(int)xv + fld * CARDI];
    }
    for (int p = tid; p < NPAIR; p += NTHREADS) {
        int i = (int)((99.0f - sqrtf(9801.0f - 8.0f * (float)p)) * 0.5f);
        i = min(max(i, 0), 48);
        while (i * (99 - i) / 2 > p) --i;
        while ((i + 1) * (98 - i) / 2 <= p) ++i;
        int j = i + 1 + (p - i * (99 - i) / 2);
        sij[p] = (unsigned short)(i | (j << 8));
    }

    const int m0 = wid * 16;
    const int g  = lane >> 2;
    const int cx = (lane & 3) * 32;
    const unsigned aBrow = sbase + OFF_B + ((lane >> 4) * 8 + (lane & 7)) * BST
                                 + ((lane >> 3) & 1) * 16;
    const unsigned onesf = (lane < 4) ? 0x3C003C00u : 0u;

    __syncthreads();

    // ---- preload B / w2 / b1 fragments (invariant across tiles & rows) ----
    unsigned Bf[4][4][4];
    #pragma unroll
    for (int kk = 0; kk < 4; kk++)
        #pragma unroll
        for (int jp = 0; jp < 4; jp++)
            ldsm4(Bf[kk][jp][0], Bf[kk][jp][1], Bf[kk][jp][2], Bf[kk][jp][3],
                  aBrow + (jp * 16) * BST + kk * 32);
    unsigned w2f[8], b1f[8];
    *(uint4*)&w2f[0] = *(const uint4*)(sb + OFF_W2F + (lane & 3) * 32);
    *(uint4*)&w2f[4] = *(const uint4*)(sb + OFF_W2F + (lane & 3) * 32 + 16);
    *(uint4*)&b1f[0] = *(const uint4*)(sb + OFF_B1F + (lane & 3) * 32);
    *(uint4*)&b1f[4] = *(const uint4*)(sb + OFF_B1F + (lane & 3) * 32 + 16);

    // ---- 20 pair tiles (10 per batch row), warp-independent ----
    #pragma unroll 1
    for (int t = 0; t < 2 * NTILES; t++) {
        const int row2 = (t >= NTILES);
        const int tt = row2 ? t - NTILES : t;
        const char* fbase = sb + OFF_F + row2 * NF * FSTB;
        float2* ls = sLS + row2 * NPAIRP;

        int pb = tt * MTILE + m0 + g;
        int q1 = min(pb, NPAIR - 1), q2 = min(pb + 8, NPAIR - 1);
        unsigned s1 = sij[q1], s2 = sij[q2];

        const uint4* fi1 = (const uint4*)(fbase + (s1 & 255) * FSTB + cx);
        const uint4* fj1 = (const uint4*)(fbase + (s1 >> 8)  * FSTB + cx);
        const uint4* fi2 = (const uint4*)(fbase + (s2 & 255) * FSTB + cx);
        const uint4* fj2 = (const uint4*)(fbase + (s2 >> 8)  * FSTB + cx);
        uint4 i1a = fi1[0], i1b = fi1[1];
        uint4 j1a = fj1[0], j1b = fj1[1];
        uint4 i2a = fi2[0], i2b = fi2[1];
        uint4 j2a = fj2[0], j2b = fj2[1];

        unsigned af[4][4];
        af[0][0] = hmul2(i1a.x, j1a.x); af[0][2] = hmul2(i1a.y, j1a.y);
        af[0][1] = hmul2(i2a.x, j2a.x); af[0][3] = hmul2(i2a.y, j2a.y);
        af[1][0] = hmul2(i1a.z, j1a.z); af[1][2] = hmul2(i1a.w, j1a.w);
        af[1][1] = hmul2(i2a.z, j2a.z); af[1][3] = hmul2(i2a.w, j2a.w);
        af[2][0] = hmul2(i1b.x, j1b.x); af[2][2] = hmul2(i1b.y, j1b.y);
        af[2][1] = hmul2(i2b.x, j2b.x); af[2][3] = hmul2(i2b.y, j2b.y);
        af[3][0] = hmul2(i1b.z, j1b.z); af[3][2] = hmul2(i1b.w, j1b.w);
        af[3][1] = hmul2(i2b.z, j2b.z); af[3][3] = hmul2(i2b.w, j2b.w);

        uint2 acc[8];
        #pragma unroll
        for (int j = 0; j < 8; j++) acc[j] = make_uint2(0u, 0u);
        float4 accS = make_float4(0.f, 0.f, 0.f, 0.f);

        #pragma unroll
        for (int kk = 0; kk < 4; kk++) {
            #pragma unroll
            for (int jp = 0; jp < 4; jp++) {
                mma_h(acc[2 * jp].x,     acc[2 * jp].y,
                      af[kk][0], af[kk][1], af[kk][2], af[kk][3],
                      Bf[kk][jp][0], Bf[kk][jp][1]);
                mma_h(acc[2 * jp + 1].x, acc[2 * jp + 1].y,
                      af[kk][0], af[kk][1], af[kk][2], af[kk][3],
                      Bf[kk][jp][2], Bf[kk][jp][3]);
            }
            mma_hf(accS, af[kk][0], af[kk][1], af[kk][2], af[kk][3], onesf, onesf);
        }

        // -- scalar epilogue: bias+relu+dot(w2) in packed f16x2, quad-reduce --
        unsigned phx = 0u, phz = 0u;
        #pragma unroll
        for (int j = 0; j < 8; j++) {
            unsigned hx = hmax2(hadd2(acc[j].x, b1f[j]), 0u);
            unsigned hz = hmax2(hadd2(acc[j].y, b1f[j]), 0u);
            phx = hfma2(hx, w2f[j], phx);
            phz = hfma2(hz, w2f[j], phz);
        }
        float2 fx = h2f2(phx), fz = h2f2(phz);
        float pl0 = fx.x + fx.y, pl1 = fz.x + fz.y;
        #pragma unroll
        for (int o = 1; o <= 2; o <<= 1) {
            pl0 += __shfl_xor_sync(0xffffffffu, pl0, o);
            pl1 += __shfl_xor_sync(0xffffffffu, pl1, o);
        }

        if ((lane & 3) == 0) {
            if (pb < NPAIR)     ls[pb]     = make_float2(pl0, accS.x);
            if (pb + 8 < NPAIR) ls[pb + 8] = make_float2(pl1, accS.z);
        }
    }
    __syncthreads();

    // ---- softmax + combine: warps 0-3 handle row b0, warps 4-7 row b0+1 ----
    const int grp = wid >> 2;                 // 0 or 1
    const int gtid = tid & 127;               // 0..127 within group
    const float2* ls = sLS + grp * NPAIRP;

    float m = -1e30f;
    for (int p = gtid; p < NPAIR; p += 128) m = fmaxf(m, ls[p].x);
    #pragma unroll
    for (int o = 16; o; o >>= 1) m = fmaxf(m, __shfl_xor_sync(0xffffffffu, m, o));
    if (lane == 0) sRed[wid] = m;
    __syncthreads();
    if ((tid & 127) == 0) {                   // tid 0 and 128
        float tv = fmaxf(fmaxf(sRed[grp * 4], sRed[grp * 4 + 1]),
                         fmaxf(sRed[grp * 4 + 2], sRed[grp * 4 + 3]));
        sM[grp] = tv;
    }
    __syncthreads();
    const float M = sM[grp];

    float es = 0.0f, ws = 0.0f;
    for (int p = gtid; p < NPAIR; p += 128) {
        float2 v = ls[p];
        float e = __expf(v.x - M);
        es += e;
        ws = fmaf(e, v.y, ws);
    }
    #pragma unroll
    for (int o = 16; o; o >>= 1) {
        es += __shfl_xor_sync(0xffffffffu, es, o);
        ws += __shfl_xor_sync(0xffffffffu, ws, o);
    }
    if (lane == 0) { sRed[8 + wid] = es; sRed[16 + wid] = ws; }
    __syncthreads();
    if ((tid & 127) == 0) {
        float ES = 0.0f, WS = 0.0f;
        #pragma unroll
        for (int w = 0; w < 4; w++) {
            ES += sRed[8 + grp * 4 + w];
            WS += sRed[16 + grp * 4 + w];
        }
        float lin = lin_b[0];
        #pragma unroll
        for (int f = 0; f < NF; f++) lin += sLinA[grp * 64 + f];
        out[b0 + grp] = lin + WS / ES;
    }
}

extern "C" void kernel_launch(void* const* d_in, const int* in_sizes, int n_in,
                              void* d_out, int out_size)
{
    const int*   x     = (const int*)d_in[0];
    const float* emb   = (const float*)d_in[1];
    const float* W1    = (const float*)d_in[2];
    const float* b1    = (const float*)d_in[3];
    const float* w2    = (const float*)d_in[4];
    const float* b2    = (const float*)d_in[5];
    const float* lin_w = (const float*)d_in[6];
    const float* lin_b = (const float*)d_in[7];
    float* out = (float*)d_out;

    static int configured = 0;
    if (!configured) {
        cudaFuncSetAttribute(afm_kernel, cudaFuncAttributeMaxDynamicSharedMemorySize,
                             SMEM_DYN);
        configured = 1;
    }
    afm_kernel<<<out_size / 2, NTHREADS, SMEM_DYN>>>(x, emb, W1, b1, w2, b2,
                                                     lin_w, lin_b, out);
}

// round 13
// speedup vs baseline: 1.4578x; 1.0024x over previous
#include <cuda_runtime.h>
#include <cuda_fp16.h>

#define NF    50
#define DIM   64
#define ATT   64
#define CARDI 10000
#define NPAIR 1225
#define NPAIRP 1232
#define NROWS 4
#define NTHREADS 256
#define MTILE 128
#define NTILES 10
#define BST   144
#define FSTB  144

#define ALIGN16(x) (((x) + 15) & ~15)

// ---- dynamic smem byte offsets (all 16B-aligned) ----
#define OFF_B    0                                   // B = W1^T: 64 x 144B
#define OFF_F    (64 * BST)                          // sF: 200 x 144B (4 rows x 50)
#define OFF_LS   ALIGN16(OFF_F + NROWS * NF * FSTB)  // float2 {logit,sum}[4*NPAIRP]
#define OFF_SIJ  ALIGN16(OFF_LS + NROWS * NPAIRP * 8)
#define OFF_W2F  ALIGN16(OFF_SIJ + NPAIRP * 2)
#define OFF_B1F  ALIGN16(OFF_W2F + 128)
#define SMEM_DYN ALIGN16(OFF_B1F + 128)

__device__ __forceinline__ unsigned smem_u32(const void* p) {
    unsigned a;
    asm("{ .reg .u64 t; cvta.to.shared.u64 t, %1; cvt.u32.u64 %0, t; }"
        : "=r"(a) : "l"(p));
    return a;
}
__device__ __forceinline__ unsigned h2pack(float lo, float hi) {
    unsigned r;
    asm("cvt.rn.f16x2.f32 %0, %1, %2;" : "=r"(r) : "f"(hi), "f"(lo));
    return r;
}
__device__ __forceinline__ unsigned hmul2(unsigned a, unsigned b) {
    unsigned r;
    asm("mul.rn.f16x2 %0, %1, %2;" : "=r"(r) : "r"(a), "r"(b));
    return r;
}
__device__ __forceinline__ unsigned hadd2(unsigned a, unsigned b) {
    unsigned r;
    asm("add.rn.f16x2 %0, %1, %2;" : "=r"(r) : "r"(a), "r"(b));
    return r;
}
__device__ __forceinline__ unsigned hmax2(unsigned a, unsigned b) {
    unsigned r;
    asm("max.f16x2 %0, %1, %2;" : "=r"(r) : "r"(a), "r"(b));
    return r;
}
__device__ __forceinline__ unsigned hfma2(unsigned a, unsigned b, unsigned c) {
    unsigned r;
    asm("fma.rn.f16x2 %0, %1, %2, %3;" : "=r"(r) : "r"(a), "r"(b), "r"(c));
    return r;
}
__device__ __forceinline__ unsigned prmt(unsigned a, unsigned b, unsigned s) {
    unsigned r;
    asm("prmt.b32 %0, %1, %2, %3;" : "=r"(r) : "r"(a), "r"(b), "r"(s));
    return r;
}
__device__ __forceinline__ float2 h2f2(unsigned h) {
    float2 f;
    asm("{ .reg .f16 lo, hi; mov.b32 {lo, hi}, %2;\n\t"
        "cvt.f32.f16 %0, lo; cvt.f32.f16 %1, hi; }"
        : "=f"(f.x), "=f"(f.y) : "r"(h));
    return f;
}
__device__ __forceinline__ void ldsm4(unsigned& r0, unsigned& r1,
                                      unsigned& r2, unsigned& r3, unsigned addr) {
    asm volatile("ldmatrix.sync.aligned.m8n8.x4.shared.b16 {%0,%1,%2,%3}, [%4];"
                 : "=r"(r0), "=r"(r1), "=r"(r2), "=r"(r3) : "r"(addr));
}
__device__ __forceinline__ void mma_h(unsigned& d0, unsigned& d1,
                                      unsigned a0, unsigned a1, unsigned a2, unsigned a3,
                                      unsigned b0, unsigned b1) {
    asm volatile(
        "mma.sync.aligned.m16n8k16.row.col.f16.f16.f16.f16 "
        "{%0,%1}, {%2,%3,%4,%5}, {%6,%7}, {%0,%1};"
        : "+r"(d0), "+r"(d1)
        : "r"(a0), "r"(a1), "r"(a2), "r"(a3), "r"(b0), "r"(b1));
}

__global__ __launch_bounds__(NTHREADS, 2)
void afm_kernel(const int* __restrict__ x32,
                const float* __restrict__ emb,
                const float* __restrict__ W1,
                const float* __restrict__ b1,
                const float* __restrict__ w2,
                const float* __restrict__ b2,
                const float* __restrict__ lin_w,
                const float* __restrict__ lin_b,
                float* __restrict__ out)
{
    extern __shared__ __align__(16) char sb[];
    float2* sLS = (float2*)(sb + OFF_LS);
    unsigned short* sij = (unsigned short*)(sb + OFF_SIJ);
    const unsigned sbase = smem_u32(sb);

    __shared__ float sLinA[NROWS * 64], sRed[32], sM[NROWS];

    const int b0 = blockIdx.x * NROWS, tid = threadIdx.x;
    const int wid = tid >> 5, lane = tid & 31;

    // int32 vs int64 index dtype probe (values < 5e5 -> int64 high words zero)
    const bool is64 = (x32[1] == 0) & (x32[3] == 0) & (x32[5] == 0) & (x32[7] == 0);
    const long long* x64 = (const long long*)x32;

    // ---- Phase A: stage embeddings for 4 rows, fragment-permuted f16 ----
    // word w (= k/2) at word offset (w&3)*8 + (w>>3)*2 + ((w>>2)&1)
    for (int q = tid; q < NROWS * NF * DIM / 4; q += NTHREADS) {
        int row = q >> 4, c4 = q & 15;           // row 0..199
        int rr = row / NF, fld = row - rr * NF;
        long long xv = is64 ? x64[(long long)(b0 + rr) * NF + fld]
                            : (long long)x32[(b0 + rr) * NF + fld];
        int gidx = (int)xv + fld * CARDI;
        float4 v = ((const float4*)(emb + (long long)gidx * DIM))[c4];
        unsigned w0 = h2pack(v.x, v.y), w1 = h2pack(v.z, v.w);
        unsigned* dst = (unsigned*)(sb + OFF_F + row * FSTB);
        int wa = 2 * c4, wb = 2 * c4 + 1;
        dst[(wa & 3) * 8 + (wa >> 3) * 2 + ((wa >> 2) & 1)] = w0;
        dst[(wb & 3) * 8 + (wb >> 3) * 2 + ((wb >> 2) & 1)] = w1;
    }
    {   // B[n][k] = W1[k][n] f16, row stride 144B
        int n = tid & 63, kg = tid >> 6;
        unsigned u[8];
        #pragma unroll
        for (int e = 0; e < 8; e++) {
            float w0 = W1[(kg * 16 + 2 * e) * ATT + n];
            float w1v = W1[(kg * 16 + 2 * e + 1) * ATT + n];
            u[e] = h2pack(w0, w1v);
        }
        char* dst = sb + OFF_B + n * BST + kg * 32;
        *(uint4*)(dst)      = make_uint4(u[0], u[1], u[2], u[3]);
        *(uint4*)(dst + 16) = make_uint4(u[4], u[5], u[6], u[7]);
    }
    if (tid < 4) {
        int c = tid;
        unsigned* wt = (unsigned*)(sb + OFF_W2F) + c * 8;
        unsigned* bt = (unsigned*)(sb + OFF_B1F) + c * 8;
        #pragma unroll
        for (int j = 0; j < 8; j++) {
            wt[j] = h2pack(w2[8 * j + 2 * c], w2[8 * j + 2 * c + 1]);
            bt[j] = h2pack(b1[8 * j + 2 * c], b1[8 * j + 2 * c + 1]);
        }
    }
    {   // linear weights for 4 rows
        int rr = tid >> 6, fld = tid & 63;
        float lv = 0.0f;
        if (fld < NF) {
            long long xv = is64 ? x64[(long long)(b0 + rr) * NF + fld]
                                : (long long)x32[(b0 + rr) * NF + fld];
            lv = lin_w[(int)xv + fld * CARDI];
        }
        sLinA[tid] = lv;
    }
    for (int p = tid; p < NPAIR; p += NTHREADS) {
        int i = (int)((99.0f - sqrtf(9801.0f - 8.0f * (float)p)) * 0.5f);
        i = min(max(i, 0), 48);
        while (i * (99 - i) / 2 > p) --i;
        while ((i + 1) * (98 - i) / 2 <= p) ++i;
        int j = i + 1 + (p - i * (99 - i) / 2);
        sij[p] = (unsigned short)(i | (j << 8));
    }

    const int m0 = wid * 16;
    const int g  = lane >> 2;
    const int cx = (lane & 3) * 32;
    const unsigned aBrow = sbase + OFF_B + ((lane >> 4) * 8 + (lane & 7)) * BST
                                 + ((lane >> 3) & 1) * 16;
    __syncthreads();

    // ---- preload B / w2 / b1 fragments (invariant across tiles & rows) ----
    unsigned Bf[4][4][4];
    #pragma unroll
    for (int kk = 0; kk < 4; kk++)
        #pragma unroll
        for (int jp = 0; jp < 4; jp++)
            ldsm4(Bf[kk][jp][0], Bf[kk][jp][1], Bf[kk][jp][2], Bf[kk][jp][3],
                  aBrow + (jp * 16) * BST + kk * 32);
    unsigned w2f[8], b1f[8];
    *(uint4*)&w2f[0] = *(const uint4*)(sb + OFF_W2F + (lane & 3) * 32);
    *(uint4*)&w2f[4] = *(const uint4*)(sb + OFF_W2F + (lane & 3) * 32 + 16);
    *(uint4*)&b1f[0] = *(const uint4*)(sb + OFF_B1F + (lane & 3) * 32);
    *(uint4*)&b1f[4] = *(const uint4*)(sb + OFF_B1F + (lane & 3) * 32 + 16);

    // ---- pair tiles: 4 rows x 10 tiles, warp-independent ----
    #pragma unroll 1
    for (int r4 = 0; r4 < NROWS; r4++) {
        const char* fbase = sb + OFF_F + r4 * NF * FSTB;
        float2* ls = sLS + r4 * NPAIRP;
        #pragma unroll 1
        for (int tt = 0; tt < NTILES; tt++) {
            int pb = tt * MTILE + m0 + g;
            int q1 = min(pb, NPAIR - 1), q2 = min(pb + 8, NPAIR - 1);
            unsigned s1 = sij[q1], s2 = sij[q2];

            const uint4* fi1 = (const uint4*)(fbase + (s1 & 255) * FSTB + cx);
            const uint4* fj1 = (const uint4*)(fbase + (s1 >> 8)  * FSTB + cx);
            const uint4* fi2 = (const uint4*)(fbase + (s2 & 255) * FSTB + cx);
            const uint4* fj2 = (const uint4*)(fbase + (s2 >> 8)  * FSTB + cx);
            uint4 i1a = fi1[0], i1b = fi1[1];
            uint4 j1a = fj1[0], j1b = fj1[1];
            uint4 i2a = fi2[0], i2b = fi2[1];
            uint4 j2a = fj2[0], j2b = fj2[1];

            unsigned af[4][4];
            af[0][0] = hmul2(i1a.x, j1a.x); af[0][2] = hmul2(i1a.y, j1a.y);
            af[0][1] = hmul2(i2a.x, j2a.x); af[0][3] = hmul2(i2a.y, j2a.y);
            af[1][0] = hmul2(i1a.z, j1a.z); af[1][2] = hmul2(i1a.w, j1a.w);
            af[1][1] = hmul2(i2a.z, j2a.z); af[1][3] = hmul2(i2a.w, j2a.w);
            af[2][0] = hmul2(i1b.x, j1b.x); af[2][2] = hmul2(i1b.y, j1b.y);
            af[2][1] = hmul2(i2b.x, j2b.x); af[2][3] = hmul2(i2b.y, j2b.y);
            af[3][0] = hmul2(i1b.z, j1b.z); af[3][2] = hmul2(i1b.w, j1b.w);
            af[3][1] = hmul2(i2b.z, j2b.z); af[3][3] = hmul2(i2b.w, j2b.w);

            uint2 acc[8];
            #pragma unroll
            for (int j = 0; j < 8; j++) acc[j] = make_uint2(0u, 0u);

            #pragma unroll
            for (int kk = 0; kk < 4; kk++) {
                #pragma unroll
                for (int jp = 0; jp < 4; jp++) {
                    mma_h(acc[2 * jp].x,     acc[2 * jp].y,
                          af[kk][0], af[kk][1], af[kk][2], af[kk][3],
                          Bf[kk][jp][0], Bf[kk][jp][1]);
                    mma_h(acc[2 * jp + 1].x, acc[2 * jp + 1].y,
                          af[kk][0], af[kk][1], af[kk][2], af[kk][3],
                          Bf[kk][jp][2], Bf[kk][jp][3]);
                }
            }

            // -- ssum from resident A fragments (f16 tree) --
            unsigned sga = hadd2(hadd2(af[0][0], af[0][2]), hadd2(af[1][0], af[1][2]));
            unsigned sgb = hadd2(hadd2(af[2][0], af[2][2]), hadd2(af[3][0], af[3][2]));
            unsigned sg  = hadd2(sga, sgb);
            unsigned s8a = hadd2(hadd2(af[0][1], af[0][3]), hadd2(af[1][1], af[1][3]));
            unsigned s8b = hadd2(hadd2(af[2][1], af[2][3]), hadd2(af[3][1], af[3][3]));
            unsigned sg8 = hadd2(s8a, s8b);
            sg  = hadd2(sg,  prmt(sg,  sg,  0x1032));
            sg8 = hadd2(sg8, prmt(sg8, sg8, 0x1032));
            unsigned packS = prmt(sg, sg8, 0x5410);

            // -- logits: bias+relu+dot(w2) in f16x2 --
            unsigned phx = 0u, phz = 0u;
            #pragma unroll
            for (int j = 0; j < 8; j++) {
                unsigned hx = hmax2(hadd2(acc[j].x, b1f[j]), 0u);
                unsigned hz = hmax2(hadd2(acc[j].y, b1f[j]), 0u);
                phx = hfma2(hx, w2f[j], phx);
                phz = hfma2(hz, w2f[j], phz);
            }
            unsigned lg  = hadd2(phx, prmt(phx, phx, 0x1032));
            unsigned lg8 = hadd2(phz, prmt(phz, phz, 0x1032));
            unsigned packL = prmt(lg, lg8, 0x5410);

            #pragma unroll
            for (int o = 1; o <= 2; o <<= 1) {
                packL = hadd2(packL, __shfl_xor_sync(0xffffffffu, packL, o));
                packS = hadd2(packS, __shfl_xor_sync(0xffffffffu, packS, o));
            }
            if ((lane & 3) == 0) {
                float2 L = h2f2(packL), S = h2f2(packS);
                if (pb < NPAIR)     ls[pb]     = make_float2(L.x, S.x);
                if (pb + 8 < NPAIR) ls[pb + 8] = make_float2(L.y, S.y);
            }
        }
    }
    __syncthreads();

    // ---- softmax + combine: 4 groups of 2 warps, one batch row each ----
    const int grp = wid >> 1;                  // 0..3
    const int gtid = tid & 63;                 // 0..63 within group
    const float2* ls = sLS + grp * NPAIRP;

    float m = -1e30f;
    for (int p = gtid; p < NPAIR; p += 64) m = fmaxf(m, ls[p].x);
    #pragma unroll
    for (int o = 16; o; o >>= 1) m = fmaxf(m, __shfl_xor_sync(0xffffffffu, m, o));
    if (lane == 0) sRed[wid] = m;
    __syncthreads();
    if (gtid == 0) sM[grp] = fmaxf(sRed[grp * 2], sRed[grp * 2 + 1]);
    __syncthreads();
    const float M = sM[grp];

    float es = 0.0f, ws = 0.0f;
    for (int p = gtid; p < NPAIR; p += 64) {
        float2 v = ls[p];
        float e = __expf(v.x - M);
        es += e;
        ws = fmaf(e, v.y, ws);
    }
    #pragma unroll
    for (int o = 16; o; o >>= 1) {
        es += __shfl_xor_sync(0xffffffffu, es, o);
        ws += __shfl_xor_sync(0xffffffffu, ws, o);
    }
    if (lane == 0) { sRed[8 + wid] = es; sRed[16 + wid] = ws; }
    __syncthreads();
    if (gtid == 0) {
        float ES = sRed[8 + grp * 2] + sRed[8 + grp * 2 + 1];
        float WS = sRed[16 + grp * 2] + sRed[16 + grp * 2 + 1];
        float lin = lin_b[0];
        #pragma unroll
        for (int f = 0; f < NF; f++) lin += sLinA[grp * 64 + f];
        out[b0 + grp] = lin + WS / ES;
    }
}

extern "C" void kernel_launch(void* const* d_in, const int* in_sizes, int n_in,
                              void* d_out, int out_size)
{
    const int*   x     = (const int*)d_in[0];
    const float* emb   = (const float*)d_in[1];
    const float* W1    = (const float*)d_in[2];
    const float* b1    = (const float*)d_in[3];
    const float* w2    = (const float*)d_in[4];
    const float* b2    = (const float*)d_in[5];
    const float* lin_w = (const float*)d_in[6];
    const float* lin_b = (const float*)d_in[7];
    float* out = (float*)d_out;

    static int configured = 0;
    if (!configured) {
        cudaFuncSetAttribute(afm_kernel, cudaFuncAttributeMaxDynamicSharedMemorySize,
                             SMEM_DYN);
        configured = 1;
    }
    afm_kernel<<<out_size / NROWS, NTHREADS, SMEM_DYN>>>(x, emb, W1, b1, w2, b2,
                                                         lin_w, lin_b, out);
}